// round 6
// baseline (speedup 1.0000x reference)
#include <cuda_runtime.h>
#include <cuda_bf16.h>
#include <cstdint>

#define BB     8
#define HH     64
#define WW     64
#define NPIX   32768
#define DIM    192
#define QKVN   576
#define HEADSB 2
#define HEADD  32
#define KEXT   384        // hi(192) | lo(192) bf16

typedef unsigned long long u64;
typedef unsigned int u32;

// Scratch (device globals: allocation-free rule)
__device__ float         g_qkv[(size_t)NPIX * QKVN];
__device__ __nv_bfloat16 g_xe[(size_t)NPIX * KEXT];
__device__ __nv_bfloat16 g_ye[(size_t)NPIX * KEXT];
__device__ __nv_bfloat16 g_wqe[(size_t)QKVN * KEXT];
__device__ __nv_bfloat16 g_wpe[(size_t)DIM * KEXT];

// ---- f32x2 helpers ---------------------------------------------------------
__device__ __forceinline__ void ffma2(u64& d, u64 a, u64 b) {
    asm("fma.rn.f32x2 %0, %1, %2, %0;" : "+l"(d) : "l"(a), "l"(b));
}
__device__ __forceinline__ u64 dup2(float v) {
    u64 r; asm("mov.b64 %0, {%1, %1};" : "=l"(r) : "f"(v)); return r;
}
__device__ __forceinline__ u64 pk2(float lo, float hi) {
    u64 r; asm("mov.b64 %0, {%1, %2};" : "=l"(r) : "f"(lo), "f"(hi)); return r;
}
__device__ __forceinline__ void unpk2(u64 v, float& lo, float& hi) {
    asm("mov.b64 {%0, %1}, %2;" : "=f"(lo), "=f"(hi) : "l"(v));
}
__device__ __forceinline__ u32 sToU32(const void* p) {
    u32 a;
    asm("{ .reg .u64 t; cvta.to.shared.u64 t, %1; cvt.u32.u64 %0, t; }" : "=r"(a) : "l"(p));
    return a;
}

// ---- warp MMA primitives ----------------------------------------------------
#define LDSM4(r, addr) \
    asm volatile("ldmatrix.sync.aligned.m8n8.x4.shared.b16 {%0,%1,%2,%3}, [%4];" \
                 : "=r"((r)[0]), "=r"((r)[1]), "=r"((r)[2]), "=r"((r)[3]) : "r"(addr))

__device__ __forceinline__ void hmma(float* c, const u32* a, u32 b0, u32 b1) {
    asm volatile(
        "mma.sync.aligned.m16n8k16.row.col.f32.bf16.bf16.f32 "
        "{%0,%1,%2,%3}, {%4,%5,%6,%7}, {%8,%9}, {%0,%1,%2,%3};"
        : "+f"(c[0]), "+f"(c[1]), "+f"(c[2]), "+f"(c[3])
        : "r"(a[0]), "r"(a[1]), "r"(a[2]), "r"(a[3]), "r"(b0), "r"(b1));
}

#define CPA16(s, g)  asm volatile("cp.async.cg.shared.global [%0], [%1], 16;" :: "r"(s), "l"(g))
#define CPA_COMMIT() asm volatile("cp.async.commit_group;" ::: "memory")
#define CPA_WAIT1()  asm volatile("cp.async.wait_group 1;" ::: "memory")
#define CPA_WAIT0()  asm volatile("cp.async.wait_group 0;" ::: "memory")

// ---------------------------------------------------------------------------
// conv_x: x[b][k][s] fp32 -> g_xe[(b,s)][k]=hi, [192+k]=lo   (32x32 transpose)
// ---------------------------------------------------------------------------
__global__ __launch_bounds__(256) void conv_x(const float* __restrict__ x) {
    __shared__ float t[32][33];
    const int tx = threadIdx.x & 31, ty = threadIdx.x >> 5;
    const int s0 = blockIdx.x * 32, k0 = blockIdx.y * 32, b = blockIdx.z;
    const float* xb = x + ((size_t)b * DIM + k0) * 4096 + s0;
    #pragma unroll
    for (int r = 0; r < 4; r++)
        t[ty + 8 * r][tx] = xb[(size_t)(ty + 8 * r) * 4096 + tx];
    __syncthreads();
    #pragma unroll
    for (int r = 0; r < 4; r++) {
        const int sl = ty + 8 * r;
        const float v = t[tx][sl];
        const __nv_bfloat16 h = __float2bfloat16(v);
        const __nv_bfloat16 l = __float2bfloat16(v - __bfloat162float(h));
        __nv_bfloat16* row = g_xe + (size_t)((b << 12) + s0 + sl) * KEXT;
        row[k0 + tx]       = h;
        row[192 + k0 + tx] = l;
    }
}

__global__ __launch_bounds__(256) void conv_w(const float* __restrict__ wq,
                                              const float* __restrict__ wp) {
    int i = blockIdx.x * 256 + threadIdx.x;
    if (i < QKVN * DIM) {
        const int n = i / DIM, k = i % DIM;
        const float v = wq[i];
        const __nv_bfloat16 h = __float2bfloat16(v);
        const __nv_bfloat16 l = __float2bfloat16(v - __bfloat162float(h));
        g_wqe[(size_t)n * KEXT + k] = h;
        g_wqe[(size_t)n * KEXT + 192 + k] = l;
    } else {
        i -= QKVN * DIM;
        if (i < DIM * DIM) {
            const int n = i / DIM, k = i % DIM;
            const float v = wp[i];
            const __nv_bfloat16 h = __float2bfloat16(v);
            const __nv_bfloat16 l = __float2bfloat16(v - __bfloat162float(h));
            g_wpe[(size_t)n * KEXT + k] = h;
            g_wpe[(size_t)n * KEXT + 192 + k] = l;
        }
    }
}

// ---------------------------------------------------------------------------
// HMMA GEMM, CTA 128x96, 8 warps, extended-K split, 2-stage cp.async pipeline.
// EPI=0: coalesced fp32 rows into g_qkv (+bias).  EPI=1: CHW out (+bias).
// ---------------------------------------------------------------------------
#define MT 128
#define NT 96
#define SMB (MT * 768)                 // 98304 (A: 128 rows x 768B)
#define SM_TOT (SMB + NT * 768)        // 172032

template<int EPI>
__global__ __launch_bounds__(256) void hmma_gemm(const __nv_bfloat16* __restrict__ A,
                                                 const __nv_bfloat16* __restrict__ Bw,
                                                 const float* __restrict__ bias,
                                                 float* __restrict__ outp) {
    extern __shared__ char smem[];
    const u32 sb = sToU32(smem);
    const int tid = threadIdx.x;
    const int wid = tid >> 5, lane = tid & 31;
    const int m0 = blockIdx.x * MT;
    const int n0 = blockIdx.y * NT;

    const __nv_bfloat16* Ab = A + (size_t)m0 * KEXT;
    const __nv_bfloat16* Bb = Bw + (size_t)n0 * KEXT;

    // phase 0: hi chunks (c < 24)
    #pragma unroll
    for (int i = 0; i < 12; i++) {
        const int idx = tid + i * 256;
        const int m = idx / 24, c = idx % 24;
        CPA16(sb + m * 768 + ((c ^ (m & 7)) << 4), Ab + (size_t)m * KEXT + c * 8);
    }
    #pragma unroll
    for (int i = 0; i < 9; i++) {
        const int idx = tid + i * 256;
        const int n = idx / 24, c = idx % 24;
        CPA16(sb + SMB + n * 768 + ((c ^ (n & 7)) << 4), Bb + (size_t)n * KEXT + c * 8);
    }
    CPA_COMMIT();
    // phase 1: lo chunks (c in 24..47)
    #pragma unroll
    for (int i = 0; i < 12; i++) {
        const int idx = tid + i * 256;
        const int m = idx / 24, c = idx % 24 + 24;
        CPA16(sb + m * 768 + ((c ^ (m & 7)) << 4), Ab + (size_t)m * KEXT + c * 8);
    }
    #pragma unroll
    for (int i = 0; i < 9; i++) {
        const int idx = tid + i * 256;
        const int n = idx / 24, c = idx % 24 + 24;
        CPA16(sb + SMB + n * 768 + ((c ^ (n & 7)) << 4), Bb + (size_t)n * KEXT + c * 8);
    }
    CPA_COMMIT();

    const int warpM = (wid >> 1) * 32;
    const int warpN = (wid & 1) * 48;
    const int lr = lane & 15;
    const int lh = lane >> 4;

    const u32 aBase = sb + (warpM + lr) * 768;
    const int asw   = lr & 7;
    u32 bBase[3]; int bsw[3];
    #pragma unroll
    for (int g = 0; g < 3; g++) {
        const int row = warpN + g * 16 + lr;
        bBase[g] = sb + SMB + row * 768;
        bsw[g]   = row & 7;
    }

    float acc[2][6][4] = {};

    CPA_WAIT1();
    __syncthreads();

    // term 0: Ahi x Bhi
    #pragma unroll
    for (int kk = 0; kk < 12; kk++) {
        const int ac = kk * 2 + lh;
        u32 af0[4], af1[4];
        LDSM4(af0, aBase + ((ac ^ asw) << 4));
        LDSM4(af1, aBase + 16 * 768 + ((ac ^ asw) << 4));
        u32 bf[3][4];
        #pragma unroll
        for (int g = 0; g < 3; g++)
            LDSM4(bf[g], bBase[g] + ((ac ^ bsw[g]) << 4));
        #pragma unroll
        for (int j = 0; j < 6; j++) {
            const int g = j >> 1, p = j & 1;
            hmma(acc[0][j], af0, bf[g][p], bf[g][p + 2]);
            hmma(acc[1][j], af1, bf[g][p], bf[g][p + 2]);
        }
    }

    CPA_WAIT0();
    __syncthreads();

    // terms 1 (Alo x Bhi) and 2 (Ahi x Blo)
    #pragma unroll
    for (int t = 1; t < 3; t++) {
        const int akb = (t == 1) ? 24 : 0;
        const int bkb = (t == 2) ? 24 : 0;
        #pragma unroll
        for (int kk = 0; kk < 12; kk++) {
            const int ac = akb + kk * 2 + lh;
            u32 af0[4], af1[4];
            LDSM4(af0, aBase + ((ac ^ asw) << 4));
            LDSM4(af1, aBase + 16 * 768 + ((ac ^ asw) << 4));
            const int bc = bkb + kk * 2 + lh;
            u32 bf[3][4];
            #pragma unroll
            for (int g = 0; g < 3; g++)
                LDSM4(bf[g], bBase[g] + ((bc ^ bsw[g]) << 4));
            #pragma unroll
            for (int j = 0; j < 6; j++) {
                const int g = j >> 1, p = j & 1;
                hmma(acc[0][j], af0, bf[g][p], bf[g][p + 2]);
                hmma(acc[1][j], af1, bf[g][p], bf[g][p + 2]);
            }
        }
    }

    __syncthreads();   // smem reuse for epilogue staging

    if (EPI == 0) {
        // stage C in smem [128][98], then coalesced row stores into g_qkv
        float* Ct = (float*)smem;
        #pragma unroll
        for (int mt = 0; mt < 2; mt++) {
            #pragma unroll
            for (int j = 0; j < 6; j++) {
                const int rm = warpM + mt * 16 + (lane >> 2);
                const int rn = warpN + j * 8 + (lane & 3) * 2;
                Ct[rm * 98 + rn]           = acc[mt][j][0];
                Ct[rm * 98 + rn + 1]       = acc[mt][j][1];
                Ct[(rm + 8) * 98 + rn]     = acc[mt][j][2];
                Ct[(rm + 8) * 98 + rn + 1] = acc[mt][j][3];
            }
        }
        __syncthreads();
        #pragma unroll
        for (int i = 0; i < 12; i++) {
            const int idx = tid + i * 256;      // 3072 float4 stores
            const int m = idx / 24, c = (idx % 24) * 4;
            const float4 bv = *(const float4*)&bias[n0 + c];
            float4 v;
            v.x = Ct[m * 98 + c]     + bv.x;
            v.y = Ct[m * 98 + c + 1] + bv.y;
            v.z = Ct[m * 98 + c + 2] + bv.z;
            v.w = Ct[m * 98 + c + 3] + bv.w;
            *(float4*)&g_qkv[(size_t)(m0 + m) * QKVN + n0 + c] = v;
        }
    } else {
        // smem transpose, coalesced CHW store
        float* Ct = (float*)smem;  // [96][132]
        #pragma unroll
        for (int mt = 0; mt < 2; mt++) {
            #pragma unroll
            for (int j = 0; j < 6; j++) {
                const int rn = warpN + j * 8 + (lane & 3) * 2;
                const int rm = warpM + mt * 16 + (lane >> 2);
                Ct[rn * 132 + rm]           = acc[mt][j][0];
                Ct[(rn + 1) * 132 + rm]     = acc[mt][j][1];
                Ct[rn * 132 + rm + 8]       = acc[mt][j][2];
                Ct[(rn + 1) * 132 + rm + 8] = acc[mt][j][3];
            }
        }
        __syncthreads();
        const int b = m0 >> 12, s0 = m0 & 4095;
        float* ob = outp + ((size_t)b * DIM + n0) * 4096 + s0;
        #pragma unroll
        for (int i = 0; i < NT * MT / 256; i++) {
            const int idx = tid + i * 256;
            const int n = idx >> 7, m = idx & 127;
            ob[(size_t)n * 4096 + m] = Ct[n * 132 + m] + bias[n0 + n];
        }
    }
}

// ---------------------------------------------------------------------------
// NATTEN: 8 lanes per pixel, BOTH heads per unit (2 independent chains -> ILP).
// Row-batched, max-free softmax. Output split bf16 hi|lo into g_ye.
// ---------------------------------------------------------------------------
template<int K, int D, int BR>
__device__ __forceinline__ void natten_body(const float* __restrict__ rpb, int blk) {
    const int sl  = threadIdx.x & 7;
    const int pix = (blk * 256 + threadIdx.x) >> 3;
    const int w = pix & 63;
    const int h = (pix >> 6) & 63;
    const int b = pix >> 12;

    const float scq = 0.17677669529663687f;
    const float* qb = g_qkv + (size_t)pix * QKVN + BR * DIM + sl * 4;
    float4 q0 = *(const float4*)qb;
    float4 q1 = *(const float4*)(qb + 32);
    q0.x *= scq; q0.y *= scq; q0.z *= scq; q0.w *= scq;
    q1.x *= scq; q1.y *= scq; q1.z *= scq; q1.w *= scq;

    const int gh = h % D, iih = h / D;
    const int Lgh = (HH - gh + D - 1) / D;
    const int sth = min(max(iih - K / 2, 0), Lgh - K);
    const int gw = w % D, iiw = w / D;
    const int Lgw = (WW - gw + D - 1) / D;
    const int stw = min(max(iiw - K / 2, 0), Lgw - K);

    const float* rp0 = rpb + (size_t)(sth - iih + K - 1) * (2 * K - 1)
                       + (stw - iiw + K - 1);
    const float* rp1 = rp0 + (2 * K - 1) * (2 * K - 1);

    const float* base = g_qkv
        + (size_t)((b << 12) + (gh + sth * D) * 64 + (gw + stw * D)) * QKVN
        + BR * DIM + 64 + sl * 4;

    const int strideW = D * QKVN;
    const int strideH = D * 64 * QKVN;

    float l0 = 0.f, l1 = 0.f;
    u64 a00 = 0, a01 = 0, a10 = 0, a11 = 0;

    #pragma unroll
    for (int kh = 0; kh < K; kh++) {
        const float* p = base + (size_t)kh * strideH;
        float s0a[K], s1a[K];
        #pragma unroll
        for (int kw = 0; kw < K; kw++) {
            const float* pk = p + (size_t)kw * strideW;
            const float4 k0 = *(const float4*)pk;
            const float4 k1 = *(const float4*)(pk + 32);
            s0a[kw] = q0.x * k0.x + q0.y * k0.y + q0.z * k0.z + q0.w * k0.w;
            s1a[kw] = q1.x * k1.x + q1.y * k1.y + q1.z * k1.z + q1.w * k1.w;
        }
        #pragma unroll
        for (int kw = 0; kw < K; kw++) {
            float s0 = s0a[kw], s1 = s1a[kw];
            s0 += __shfl_xor_sync(0xffffffffu, s0, 4);
            s1 += __shfl_xor_sync(0xffffffffu, s1, 4);
            s0 += __shfl_xor_sync(0xffffffffu, s0, 2);
            s1 += __shfl_xor_sync(0xffffffffu, s1, 2);
            s0 += __shfl_xor_sync(0xffffffffu, s0, 1);
            s1 += __shfl_xor_sync(0xffffffffu, s1, 1);
            s0a[kw] = __expf(s0 + rp0[kh * (2 * K - 1) + kw]);
            s1a[kw] = __expf(s1 + rp1[kh * (2 * K - 1) + kw]);
        }
        #pragma unroll
        for (int kw = 0; kw < K; kw++) {
            const float* pv = p + (size_t)kw * strideW + 64;
            const float4 v0 = *(const float4*)pv;
            const float4 v1 = *(const float4*)(pv + 32);
            const float p0 = s0a[kw], p1 = s1a[kw];
            l0 += p0; l1 += p1;
            const u64 d0 = dup2(p0), d1 = dup2(p1);
            ffma2(a00, pk2(v0.x, v0.y), d0);
            ffma2(a01, pk2(v0.z, v0.w), d0);
            ffma2(a10, pk2(v1.x, v1.y), d1);
            ffma2(a11, pk2(v1.z, v1.w), d1);
        }
    }

    const float r0 = __frcp_rn(l0), r1 = __frcp_rn(l1);
    float o0[4], o1[4];
    unpk2(a00, o0[0], o0[1]); unpk2(a01, o0[2], o0[3]);
    unpk2(a10, o1[0], o1[1]); unpk2(a11, o1[2], o1[3]);

    __nv_bfloat16* yr = g_ye + (size_t)pix * KEXT;
    const int c0 = BR * 64 + sl * 4;
    __nv_bfloat16 h0[4], lo0[4], h1[4], lo1[4];
    #pragma unroll
    for (int i = 0; i < 4; i++) {
        const float v0 = o0[i] * r0;
        h0[i]  = __float2bfloat16(v0);
        lo0[i] = __float2bfloat16(v0 - __bfloat162float(h0[i]));
        const float v1 = o1[i] * r1;
        h1[i]  = __float2bfloat16(v1);
        lo1[i] = __float2bfloat16(v1 - __bfloat162float(h1[i]));
    }
    *(u64*)(yr + c0)            = *(const u64*)h0;
    *(u64*)(yr + 192 + c0)      = *(const u64*)lo0;
    *(u64*)(yr + c0 + 32)       = *(const u64*)h1;
    *(u64*)(yr + 192 + c0 + 32) = *(const u64*)lo1;
}

#define ABLOCKS (NPIX / 32)   // 1024 blocks per branch (32 pixels/block)

__global__ __launch_bounds__(256) void natten_all(const float* __restrict__ rpb0,
                                                  const float* __restrict__ rpb1,
                                                  const float* __restrict__ rpb2) {
    const int br  = blockIdx.x % 3;     // stripe branches across SMs
    const int idx = blockIdx.x / 3;
    if (br == 0)      natten_body<3, 1, 0>(rpb0, idx);
    else if (br == 1) natten_body<5, 2, 1>(rpb1, idx);
    else              natten_body<7, 3, 2>(rpb2, idx);
}

// ---------------------------------------------------------------------------
extern "C" void kernel_launch(void* const* d_in, const int* in_sizes, int n_in,
                              void* d_out, int out_size) {
    const float* x      = (const float*)d_in[0];
    const float* qkv_w  = (const float*)d_in[1];
    const float* qkv_b  = (const float*)d_in[2];
    const float* proj_w = (const float*)d_in[3];
    const float* proj_b = (const float*)d_in[4];
    const float* rpb0   = (const float*)d_in[5];
    const float* rpb1   = (const float*)d_in[6];
    const float* rpb2   = (const float*)d_in[7];
    float* out = (float*)d_out;

    static int smem_set = 0;
    if (!smem_set) {
        cudaFuncSetAttribute(hmma_gemm<0>, cudaFuncAttributeMaxDynamicSharedMemorySize, SM_TOT);
        cudaFuncSetAttribute(hmma_gemm<1>, cudaFuncAttributeMaxDynamicSharedMemorySize, SM_TOT);
        smem_set = 1;
    }

    __nv_bfloat16* xe  = nullptr; cudaGetSymbolAddress((void**)&xe,  g_xe);
    __nv_bfloat16* ye  = nullptr; cudaGetSymbolAddress((void**)&ye,  g_ye);
    __nv_bfloat16* wqe = nullptr; cudaGetSymbolAddress((void**)&wqe, g_wqe);
    __nv_bfloat16* wpe = nullptr; cudaGetSymbolAddress((void**)&wpe, g_wpe);

    conv_x<<<dim3(128, 6, 8), 256>>>(x);
    conv_w<<<576, 256>>>(qkv_w, proj_w);

    hmma_gemm<0><<<dim3(NPIX / MT, QKVN / NT), 256, SM_TOT>>>(xe, wqe, qkv_b, nullptr);

    natten_all<<<3 * ABLOCKS, 256>>>(rpb0, rpb1, rpb2);

    hmma_gemm<1><<<dim3(NPIX / MT, DIM / NT), 256, SM_TOT>>>(ye, wpe, proj_b, out);
}

// round 7
// speedup vs baseline: 1.1432x; 1.1432x over previous
#include <cuda_runtime.h>
#include <cuda_bf16.h>
#include <cstdint>

#define BB     8
#define HH     64
#define WW     64
#define NPIX   32768
#define DIM    192
#define QKVN   576
#define HEADSB 2
#define HEADD  32
#define KEXT   384        // hi(192) | lo(192) bf16

typedef unsigned long long u64;
typedef unsigned int u32;

// Scratch (device globals: allocation-free rule)
__device__ float         g_q[(size_t)NPIX * DIM];          // pre-scaled q, [pix][192]
__device__ float         g_kv[(size_t)3 * NPIX * 128];     // [branch][pix][k64|v64]
__device__ __nv_bfloat16 g_xe[(size_t)NPIX * KEXT];
__device__ __nv_bfloat16 g_ye[(size_t)NPIX * KEXT];
__device__ __nv_bfloat16 g_wqe[(size_t)QKVN * KEXT];
__device__ __nv_bfloat16 g_wpe[(size_t)DIM * KEXT];

// ---- f32x2 helpers ---------------------------------------------------------
__device__ __forceinline__ void ffma2(u64& d, u64 a, u64 b) {
    asm("fma.rn.f32x2 %0, %1, %2, %0;" : "+l"(d) : "l"(a), "l"(b));
}
__device__ __forceinline__ u64 dup2(float v) {
    u64 r; asm("mov.b64 %0, {%1, %1};" : "=l"(r) : "f"(v)); return r;
}
__device__ __forceinline__ u64 pk2(float lo, float hi) {
    u64 r; asm("mov.b64 %0, {%1, %2};" : "=l"(r) : "f"(lo), "f"(hi)); return r;
}
__device__ __forceinline__ void unpk2(u64 v, float& lo, float& hi) {
    asm("mov.b64 {%0, %1}, %2;" : "=f"(lo), "=f"(hi) : "l"(v));
}
__device__ __forceinline__ u32 sToU32(const void* p) {
    u32 a;
    asm("{ .reg .u64 t; cvta.to.shared.u64 t, %1; cvt.u32.u64 %0, t; }" : "=r"(a) : "l"(p));
    return a;
}

// ---- warp MMA primitives ----------------------------------------------------
#define LDSM4(r, addr) \
    asm volatile("ldmatrix.sync.aligned.m8n8.x4.shared.b16 {%0,%1,%2,%3}, [%4];" \
                 : "=r"((r)[0]), "=r"((r)[1]), "=r"((r)[2]), "=r"((r)[3]) : "r"(addr))

__device__ __forceinline__ void hmma(float* c, const u32* a, u32 b0, u32 b1) {
    asm volatile(
        "mma.sync.aligned.m16n8k16.row.col.f32.bf16.bf16.f32 "
        "{%0,%1,%2,%3}, {%4,%5,%6,%7}, {%8,%9}, {%0,%1,%2,%3};"
        : "+f"(c[0]), "+f"(c[1]), "+f"(c[2]), "+f"(c[3])
        : "r"(a[0]), "r"(a[1]), "r"(a[2]), "r"(a[3]), "r"(b0), "r"(b1));
}

#define CPA16(s, g)  asm volatile("cp.async.cg.shared.global [%0], [%1], 16;" :: "r"(s), "l"(g))
#define CPA_COMMIT() asm volatile("cp.async.commit_group;" ::: "memory")
#define CPA_WAIT1()  asm volatile("cp.async.wait_group 1;" ::: "memory")
#define CPA_WAIT0()  asm volatile("cp.async.wait_group 0;" ::: "memory")

// ---------------------------------------------------------------------------
// conv_x: x[b][k][s] fp32 -> g_xe[(b,s)][k]=hi, [192+k]=lo   (32x32 transpose)
// ---------------------------------------------------------------------------
__global__ __launch_bounds__(256) void conv_x(const float* __restrict__ x) {
    __shared__ float t[32][33];
    const int tx = threadIdx.x & 31, ty = threadIdx.x >> 5;
    const int s0 = blockIdx.x * 32, k0 = blockIdx.y * 32, b = blockIdx.z;
    const float* xb = x + ((size_t)b * DIM + k0) * 4096 + s0;
    #pragma unroll
    for (int r = 0; r < 4; r++)
        t[ty + 8 * r][tx] = xb[(size_t)(ty + 8 * r) * 4096 + tx];
    __syncthreads();
    #pragma unroll
    for (int r = 0; r < 4; r++) {
        const int sl = ty + 8 * r;
        const float v = t[tx][sl];
        const __nv_bfloat16 h = __float2bfloat16(v);
        const __nv_bfloat16 l = __float2bfloat16(v - __bfloat162float(h));
        __nv_bfloat16* row = g_xe + (size_t)((b << 12) + s0 + sl) * KEXT;
        row[k0 + tx]       = h;
        row[192 + k0 + tx] = l;
    }
}

__global__ __launch_bounds__(256) void conv_w(const float* __restrict__ wq,
                                              const float* __restrict__ wp) {
    int i = blockIdx.x * 256 + threadIdx.x;
    if (i < QKVN * DIM) {
        const int n = i / DIM, k = i % DIM;
        const float v = wq[i];
        const __nv_bfloat16 h = __float2bfloat16(v);
        const __nv_bfloat16 l = __float2bfloat16(v - __bfloat162float(h));
        g_wqe[(size_t)n * KEXT + k] = h;
        g_wqe[(size_t)n * KEXT + 192 + k] = l;
    } else {
        i -= QKVN * DIM;
        if (i < DIM * DIM) {
            const int n = i / DIM, k = i % DIM;
            const float v = wp[i];
            const __nv_bfloat16 h = __float2bfloat16(v);
            const __nv_bfloat16 l = __float2bfloat16(v - __bfloat162float(h));
            g_wpe[(size_t)n * KEXT + k] = h;
            g_wpe[(size_t)n * KEXT + 192 + k] = l;
        }
    }
}

// ---------------------------------------------------------------------------
// HMMA GEMM, CTA 128x96, 8 warps, extended-K split, 2-stage cp.async pipeline.
// EPI=0: routed stores -> g_q (scaled q) + g_kv packed.  EPI=1: CHW out.
// ---------------------------------------------------------------------------
#define MT 128
#define NT 96
#define SMB (MT * 768)                 // 98304 (A: 128 rows x 768B)
#define SM_TOT (SMB + NT * 768)        // 172032

template<int EPI>
__global__ __launch_bounds__(256) void hmma_gemm(const __nv_bfloat16* __restrict__ A,
                                                 const __nv_bfloat16* __restrict__ Bw,
                                                 const float* __restrict__ bias,
                                                 float* __restrict__ outp) {
    extern __shared__ char smem[];
    const u32 sb = sToU32(smem);
    const int tid = threadIdx.x;
    const int wid = tid >> 5, lane = tid & 31;
    const int m0 = blockIdx.x * MT;
    const int n0 = blockIdx.y * NT;

    const __nv_bfloat16* Ab = A + (size_t)m0 * KEXT;
    const __nv_bfloat16* Bb = Bw + (size_t)n0 * KEXT;

    // phase 0: hi chunks (c < 24)
    #pragma unroll
    for (int i = 0; i < 12; i++) {
        const int idx = tid + i * 256;
        const int m = idx / 24, c = idx % 24;
        CPA16(sb + m * 768 + ((c ^ (m & 7)) << 4), Ab + (size_t)m * KEXT + c * 8);
    }
    #pragma unroll
    for (int i = 0; i < 9; i++) {
        const int idx = tid + i * 256;
        const int n = idx / 24, c = idx % 24;
        CPA16(sb + SMB + n * 768 + ((c ^ (n & 7)) << 4), Bb + (size_t)n * KEXT + c * 8);
    }
    CPA_COMMIT();
    // phase 1: lo chunks (c in 24..47)
    #pragma unroll
    for (int i = 0; i < 12; i++) {
        const int idx = tid + i * 256;
        const int m = idx / 24, c = idx % 24 + 24;
        CPA16(sb + m * 768 + ((c ^ (m & 7)) << 4), Ab + (size_t)m * KEXT + c * 8);
    }
    #pragma unroll
    for (int i = 0; i < 9; i++) {
        const int idx = tid + i * 256;
        const int n = idx / 24, c = idx % 24 + 24;
        CPA16(sb + SMB + n * 768 + ((c ^ (n & 7)) << 4), Bb + (size_t)n * KEXT + c * 8);
    }
    CPA_COMMIT();

    const int warpM = (wid >> 1) * 32;
    const int warpN = (wid & 1) * 48;
    const int lr = lane & 15;
    const int lh = lane >> 4;

    const u32 aBase = sb + (warpM + lr) * 768;
    const int asw   = lr & 7;
    u32 bBase[3]; int bsw[3];
    #pragma unroll
    for (int g = 0; g < 3; g++) {
        const int row = warpN + g * 16 + lr;
        bBase[g] = sb + SMB + row * 768;
        bsw[g]   = row & 7;
    }

    float acc[2][6][4] = {};

    CPA_WAIT1();
    __syncthreads();

    // term 0: Ahi x Bhi
    #pragma unroll
    for (int kk = 0; kk < 12; kk++) {
        const int ac = kk * 2 + lh;
        u32 af0[4], af1[4];
        LDSM4(af0, aBase + ((ac ^ asw) << 4));
        LDSM4(af1, aBase + 16 * 768 + ((ac ^ asw) << 4));
        u32 bf[3][4];
        #pragma unroll
        for (int g = 0; g < 3; g++)
            LDSM4(bf[g], bBase[g] + ((ac ^ bsw[g]) << 4));
        #pragma unroll
        for (int j = 0; j < 6; j++) {
            const int g = j >> 1, p = j & 1;
            hmma(acc[0][j], af0, bf[g][p], bf[g][p + 2]);
            hmma(acc[1][j], af1, bf[g][p], bf[g][p + 2]);
        }
    }

    CPA_WAIT0();
    __syncthreads();

    // terms 1 (Alo x Bhi) and 2 (Ahi x Blo)
    #pragma unroll
    for (int t = 1; t < 3; t++) {
        const int akb = (t == 1) ? 24 : 0;
        const int bkb = (t == 2) ? 24 : 0;
        #pragma unroll
        for (int kk = 0; kk < 12; kk++) {
            const int ac = akb + kk * 2 + lh;
            u32 af0[4], af1[4];
            LDSM4(af0, aBase + ((ac ^ asw) << 4));
            LDSM4(af1, aBase + 16 * 768 + ((ac ^ asw) << 4));
            const int bc = bkb + kk * 2 + lh;
            u32 bf[3][4];
            #pragma unroll
            for (int g = 0; g < 3; g++)
                LDSM4(bf[g], bBase[g] + ((bc ^ bsw[g]) << 4));
            #pragma unroll
            for (int j = 0; j < 6; j++) {
                const int g = j >> 1, p = j & 1;
                hmma(acc[0][j], af0, bf[g][p], bf[g][p + 2]);
                hmma(acc[1][j], af1, bf[g][p], bf[g][p + 2]);
            }
        }
    }

    __syncthreads();   // smem reuse for epilogue staging

    if (EPI == 0) {
        // stage C in smem [128][98], then coalesced routed float4 stores
        float* Ct = (float*)smem;
        #pragma unroll
        for (int mt = 0; mt < 2; mt++) {
            #pragma unroll
            for (int j = 0; j < 6; j++) {
                const int rm = warpM + mt * 16 + (lane >> 2);
                const int rn = warpN + j * 8 + (lane & 3) * 2;
                Ct[rm * 98 + rn]           = acc[mt][j][0];
                Ct[rm * 98 + rn + 1]       = acc[mt][j][1];
                Ct[(rm + 8) * 98 + rn]     = acc[mt][j][2];
                Ct[(rm + 8) * 98 + rn + 1] = acc[mt][j][3];
            }
        }
        __syncthreads();
        const float qsc = 0.17677669529663687f;
        #pragma unroll
        for (int i = 0; i < 12; i++) {
            const int idx = tid + i * 256;      // 3072 float4 stores
            const int m = idx / 24, c = (idx % 24) * 4;
            const int n = n0 + c;
            const int br = n / 192, r = n % 192;
            const int sec = r >> 6, off = r & 63;
            const float4 bv = *(const float4*)&bias[n];
            float4 v;
            v.x = Ct[m * 98 + c]     + bv.x;
            v.y = Ct[m * 98 + c + 1] + bv.y;
            v.z = Ct[m * 98 + c + 2] + bv.z;
            v.w = Ct[m * 98 + c + 3] + bv.w;
            const int pix = m0 + m;
            if (sec == 0) {
                v.x *= qsc; v.y *= qsc; v.z *= qsc; v.w *= qsc;
                *(float4*)&g_q[(size_t)pix * DIM + br * 64 + off] = v;
            } else {
                *(float4*)&g_kv[((size_t)(br << 15) + pix) * 128 + (sec - 1) * 64 + off] = v;
            }
        }
    } else {
        // smem transpose, coalesced CHW store
        float* Ct = (float*)smem;  // [96][132]
        #pragma unroll
        for (int mt = 0; mt < 2; mt++) {
            #pragma unroll
            for (int j = 0; j < 6; j++) {
                const int rn = warpN + j * 8 + (lane & 3) * 2;
                const int rm = warpM + mt * 16 + (lane >> 2);
                Ct[rn * 132 + rm]           = acc[mt][j][0];
                Ct[(rn + 1) * 132 + rm]     = acc[mt][j][1];
                Ct[rn * 132 + rm + 8]       = acc[mt][j][2];
                Ct[(rn + 1) * 132 + rm + 8] = acc[mt][j][3];
            }
        }
        __syncthreads();
        const int b = m0 >> 12, s0 = m0 & 4095;
        float* ob = outp + ((size_t)b * DIM + n0) * 4096 + s0;
        #pragma unroll
        for (int i = 0; i < NT * MT / 256; i++) {
            const int idx = tid + i * 256;
            const int n = idx >> 7, m = idx & 127;
            ob[(size_t)n * 4096 + m] = Ct[n * 132 + m] + bias[n0 + n];
        }
    }
}

// ---------------------------------------------------------------------------
// NATTEN (R5 structure): 8 lanes per (pixel, head), packed g_kv layout.
// Row-batched, max-free softmax. Output split bf16 hi|lo into g_ye.
// ---------------------------------------------------------------------------
template<int K, int D, int BR>
__device__ __forceinline__ void natten_body(const float* __restrict__ rpb, int blk) {
    const int sl   = threadIdx.x & 7;
    const int gid  = (blk * 256 + threadIdx.x) >> 3;
    const int head = gid & 1;
    const int pix  = gid >> 1;
    const int w = pix & 63;
    const int h = (pix >> 6) & 63;
    const int b = pix >> 12;

    const float4 q = *(const float4*)&g_q[(size_t)pix * DIM + BR * 64 + head * HEADD + sl * 4];

    const int gh = h % D, iih = h / D;
    const int Lgh = (HH - gh + D - 1) / D;
    const int sth = min(max(iih - K / 2, 0), Lgh - K);
    const int gw = w % D, iiw = w / D;
    const int Lgw = (WW - gw + D - 1) / D;
    const int stw = min(max(iiw - K / 2, 0), Lgw - K);

    const float* rpbh = rpb + (size_t)head * (2 * K - 1) * (2 * K - 1)
                       + (size_t)(sth - iih + K - 1) * (2 * K - 1)
                       + (stw - iiw + K - 1);

    const float* base = g_kv
        + ((size_t)(BR << 15) + (b << 12) + (gh + sth * D) * 64 + (gw + stw * D)) * 128
        + head * HEADD + sl * 4;

    const int strideW = D * 128;
    const int strideH = D * 64 * 128;

    float l = 0.f;
    u64 acc0 = 0, acc1 = 0;

    #pragma unroll
    for (int kh = 0; kh < K; kh++) {
        const float* p = base + (size_t)kh * strideH;
        float sarr[K];
        #pragma unroll
        for (int kw = 0; kw < K; kw++) {
            const float4 k4 = *(const float4*)(p + (size_t)kw * strideW);
            sarr[kw] = q.x * k4.x + q.y * k4.y + q.z * k4.z + q.w * k4.w;
        }
        #pragma unroll
        for (int kw = 0; kw < K; kw++) {
            float s = sarr[kw];
            s += __shfl_xor_sync(0xffffffffu, s, 4);
            s += __shfl_xor_sync(0xffffffffu, s, 2);
            s += __shfl_xor_sync(0xffffffffu, s, 1);
            sarr[kw] = __expf(s + rpbh[kh * (2 * K - 1) + kw]);
        }
        #pragma unroll
        for (int kw = 0; kw < K; kw++) {
            const float4 v4 = *(const float4*)(p + (size_t)kw * strideW + 64);
            const float pr = sarr[kw];
            l += pr;
            const u64 prd = dup2(pr);
            ffma2(acc0, pk2(v4.x, v4.y), prd);
            ffma2(acc1, pk2(v4.z, v4.w), prd);
        }
    }
    const float rinv = __frcp_rn(l);
    float o[4];
    unpk2(acc0, o[0], o[1]);
    unpk2(acc1, o[2], o[3]);

    const int c = BR * 64 + head * HEADD + sl * 4;
    __nv_bfloat16 hi[4], lo[4];
    #pragma unroll
    for (int i = 0; i < 4; i++) {
        const float v = o[i] * rinv;
        hi[i] = __float2bfloat16(v);
        lo[i] = __float2bfloat16(v - __bfloat162float(hi[i]));
    }
    __nv_bfloat16* yr = g_ye + (size_t)pix * KEXT;
    *(u64*)(yr + c)       = *(const u64*)hi;
    *(u64*)(yr + 192 + c) = *(const u64*)lo;
}

#define ABLOCKS (NPIX * HEADSB / 32)   // 2048 blocks per branch

__global__ __launch_bounds__(256) void natten_all(const float* __restrict__ rpb0,
                                                  const float* __restrict__ rpb1,
                                                  const float* __restrict__ rpb2) {
    const int bb = blockIdx.x;
    if (bb < ABLOCKS)          natten_body<3, 1, 0>(rpb0, bb);
    else if (bb < 2 * ABLOCKS) natten_body<5, 2, 1>(rpb1, bb - ABLOCKS);
    else                       natten_body<7, 3, 2>(rpb2, bb - 2 * ABLOCKS);
}

// ---------------------------------------------------------------------------
extern "C" void kernel_launch(void* const* d_in, const int* in_sizes, int n_in,
                              void* d_out, int out_size) {
    const float* x      = (const float*)d_in[0];
    const float* qkv_w  = (const float*)d_in[1];
    const float* qkv_b  = (const float*)d_in[2];
    const float* proj_w = (const float*)d_in[3];
    const float* proj_b = (const float*)d_in[4];
    const float* rpb0   = (const float*)d_in[5];
    const float* rpb1   = (const float*)d_in[6];
    const float* rpb2   = (const float*)d_in[7];
    float* out = (float*)d_out;

    static int smem_set = 0;
    if (!smem_set) {
        cudaFuncSetAttribute(hmma_gemm<0>, cudaFuncAttributeMaxDynamicSharedMemorySize, SM_TOT);
        cudaFuncSetAttribute(hmma_gemm<1>, cudaFuncAttributeMaxDynamicSharedMemorySize, SM_TOT);
        smem_set = 1;
    }

    __nv_bfloat16* xe  = nullptr; cudaGetSymbolAddress((void**)&xe,  g_xe);
    __nv_bfloat16* ye  = nullptr; cudaGetSymbolAddress((void**)&ye,  g_ye);
    __nv_bfloat16* wqe = nullptr; cudaGetSymbolAddress((void**)&wqe, g_wqe);
    __nv_bfloat16* wpe = nullptr; cudaGetSymbolAddress((void**)&wpe, g_wpe);

    conv_x<<<dim3(128, 6, 8), 256>>>(x);
    conv_w<<<576, 256>>>(qkv_w, proj_w);

    hmma_gemm<0><<<dim3(NPIX / MT, QKVN / NT), 256, SM_TOT>>>(xe, wqe, qkv_b, nullptr);

    natten_all<<<3 * ABLOCKS, 256>>>(rpb0, rpb1, rpb2);

    hmma_gemm<1><<<dim3(NPIX / MT, DIM / NT), 256, SM_TOT>>>(ye, wpe, proj_b, out);
}